// round 13
// baseline (speedup 1.0000x reference)
#include <cuda_runtime.h>
#include <math.h>

#define D_MODEL 1024
#define SEQ     4096
#define NHEAD   16
#define DK      64

// Scratch (allocation-free: __device__ globals)
__device__ float g_Q[SEQ * D_MODEL];
__device__ float g_K[SEQ * D_MODEL];
__device__ float g_V[SEQ * D_MODEL];
__device__ float g_O[SEQ * D_MODEL];

// ---------------------------------------------------------------------------
// tf32 helpers. cvt.rna (round-to-nearest) is REQUIRED: raw-bit truncation in
// the mma gives a correlated -2^-11 bias per operand -> ~1e-3 systematic error.
// ---------------------------------------------------------------------------
__device__ __forceinline__ unsigned f2tf(float x) {
    unsigned y;
    asm("cvt.rna.tf32.f32 %0, %1;" : "=r"(y) : "f"(x));
    return y;
}

// D += A(16x8) * B(8x8), tf32 in, fp32 accum
__device__ __forceinline__ void mma8(float* d, const unsigned* a, const unsigned* b) {
    asm volatile(
        "mma.sync.aligned.m16n8k8.row.col.f32.tf32.tf32.f32 "
        "{%0,%1,%2,%3}, {%4,%5,%6,%7}, {%8,%9}, {%0,%1,%2,%3};\n"
        : "+f"(d[0]), "+f"(d[1]), "+f"(d[2]), "+f"(d[3])
        : "r"(a[0]), "r"(a[1]), "r"(a[2]), "r"(a[3]), "r"(b[0]), "r"(b[1]));
}

// Permutation within each 8-wide k-block so that the (c, c+4) fragment pair is
// adjacent in smem -> every fragment load is one LDS.64.
__device__ __forceinline__ int kperm(int k) {
    return (k & ~7) + ((k & 3) << 1) + ((k >> 2) & 1);
}

// 16-byte async copy global -> shared (raw bits, no conversion)
__device__ __forceinline__ void cp16(void* smem_dst, const void* gsrc) {
    unsigned saddr = (unsigned)__cvta_generic_to_shared(smem_dst);
    asm volatile("cp.async.ca.shared.global [%0], [%1], 16;"
                 :: "r"(saddr), "l"(gsrc));
}

// ============================================================================
// GEMM core: C[M,1024] = A[M,1024] @ W[1024,1024]^T + bias  (tf32 mma, NT)
// Tile 128x128x16, 8 warps as 2(M)x4(N), warp tile 64x32.
// DOUBLE-BUFFERED smem: one __syncthreads per 16-k slab.  (UNCHANGED - proven)
// ============================================================================
#define GSTR 24
#define GBUF (128 * GSTR)

__device__ __forceinline__ void gemm_store_slab(unsigned* ad, unsigned* bd,
                                                float4 av0, float4 av1,
                                                float4 wv0, float4 wv1) {
    const float aj[8] = {av0.x, av0.y, av0.z, av0.w, av1.x, av1.y, av1.z, av1.w};
    const float wj[8] = {wv0.x, wv0.y, wv0.z, wv0.w, wv1.x, wv1.y, wv1.z, wv1.w};
#pragma unroll
    for (int j = 0; j < 8; j++) {
        const int p = ((j & 3) << 1) + (j >> 2);
        ad[p] = f2tf(aj[j]);
        bd[p] = f2tf(wj[j]);
    }
}

__device__ __forceinline__ void gemm_core(const float* __restrict__ A,
                                          const float* __restrict__ W,
                                          const float* __restrict__ bias,
                                          float* __restrict__ C,
                                          int bx, int by) {
    extern __shared__ unsigned gsm[];
    unsigned* As = gsm;              // [2][128*GSTR]
    unsigned* Bs = gsm + 2 * GBUF;   // [2][128*GSTR]

    const int tid  = threadIdx.x;
    const int lane = tid & 31;
    const int warp = tid >> 5;
    const int g = lane >> 2, c = lane & 3;
    const int wm = (warp >> 2) * 64;
    const int wn = (warp & 3) * 32;
    const int bm = by * 128;
    const int bn = bx * 128;

    const int srow = tid >> 1;
    const int sk   = (tid & 1) * 8;
    const float* Ap = A + (bm + srow) * D_MODEL + sk;
    const float* Wp = W + (bn + srow) * D_MODEL + sk;
    unsigned* adst = As + srow * GSTR + sk;
    unsigned* bdst = Bs + srow * GSTR + sk;

    float acc[4][4][4];
#pragma unroll
    for (int i = 0; i < 4; i++)
#pragma unroll
        for (int j = 0; j < 4; j++)
#pragma unroll
            for (int r = 0; r < 4; r++) acc[i][j][r] = 0.0f;

    {
        float4 av0 = *(const float4*)Ap;
        float4 av1 = *(const float4*)(Ap + 4);
        float4 wv0 = *(const float4*)Wp;
        float4 wv1 = *(const float4*)(Wp + 4);
        gemm_store_slab(adst, bdst, av0, av1, wv0, wv1);
    }
    __syncthreads();

    for (int k0 = 0; k0 < D_MODEL; k0 += 16) {
        const int buf = (k0 >> 4) & 1;
        const unsigned* Acur = As + buf * GBUF;
        const unsigned* Bcur = Bs + buf * GBUF;
        const bool more = (k0 + 16) < D_MODEL;

        float4 av0, av1, wv0, wv1;
        if (more) {
            av0 = *(const float4*)(Ap + k0 + 16);
            av1 = *(const float4*)(Ap + k0 + 20);
            wv0 = *(const float4*)(Wp + k0 + 16);
            wv1 = *(const float4*)(Wp + k0 + 20);
        }

#pragma unroll
        for (int s = 0; s < 2; s++) {
            unsigned af[4][4], bf[4][2];
#pragma unroll
            for (int ma = 0; ma < 4; ma++) {
                const uint2 t0 = *(const uint2*)(Acur + (wm + ma * 16 + g)     * GSTR + s * 8 + c * 2);
                const uint2 t1 = *(const uint2*)(Acur + (wm + ma * 16 + g + 8) * GSTR + s * 8 + c * 2);
                af[ma][0] = t0.x; af[ma][1] = t1.x; af[ma][2] = t0.y; af[ma][3] = t1.y;
            }
#pragma unroll
            for (int na = 0; na < 4; na++) {
                const uint2 t = *(const uint2*)(Bcur + (wn + na * 8 + g) * GSTR + s * 8 + c * 2);
                bf[na][0] = t.x; bf[na][1] = t.y;
            }
#pragma unroll
            for (int ma = 0; ma < 4; ma++)
#pragma unroll
                for (int na = 0; na < 4; na++)
                    mma8(acc[ma][na], af[ma], bf[na]);
        }

        if (more)
            gemm_store_slab(adst + (buf ^ 1) * GBUF, bdst + (buf ^ 1) * GBUF,
                            av0, av1, wv0, wv1);
        __syncthreads();
    }

#pragma unroll
    for (int na = 0; na < 4; na++) {
        const int col = bn + wn + na * 8 + 2 * c;
        const float2 bb = *(const float2*)(bias + col);
#pragma unroll
        for (int ma = 0; ma < 4; ma++) {
            const int r0 = bm + wm + ma * 16 + g;
            float2 v0 = {acc[ma][na][0] + bb.x, acc[ma][na][1] + bb.y};
            float2 v1 = {acc[ma][na][2] + bb.x, acc[ma][na][3] + bb.y};
            *(float2*)(C + r0 * D_MODEL + col)       = v0;
            *(float2*)(C + (r0 + 8) * D_MODEL + col) = v1;
        }
    }
}

// Fused Q/K/V projection: blockIdx.z selects {query,key,value} x {Wq,Wk,Wv}.
__global__ __launch_bounds__(256, 2)
void gemm_qkv(const float* __restrict__ xq, const float* __restrict__ xk,
              const float* __restrict__ xv,
              const float* __restrict__ Wq, const float* __restrict__ bq,
              const float* __restrict__ Wk, const float* __restrict__ bk,
              const float* __restrict__ Wv, const float* __restrict__ bv,
              float* __restrict__ Cq, float* __restrict__ Ck, float* __restrict__ Cv) {
    const float *A, *W, *b;
    float* C;
    if (blockIdx.z == 0)      { A = xq; W = Wq; b = bq; C = Cq; }
    else if (blockIdx.z == 1) { A = xk; W = Wk; b = bk; C = Ck; }
    else                      { A = xv; W = Wv; b = bv; C = Cv; }
    gemm_core(A, W, b, C, blockIdx.x, blockIdx.y);
}

__global__ __launch_bounds__(256, 2)
void gemm_one(const float* __restrict__ A, const float* __restrict__ W,
              const float* __restrict__ bias, float* __restrict__ C) {
    gemm_core(A, W, bias, C, blockIdx.x, blockIdx.y);
}

// ============================================================================
// Flash attention, tf32 mma. One CTA = (head, 128-query block), 2 CTAs/SM.
// 8 warps, each owns 16 query rows -> softmax warp-local. 64-key blocks.
// Latency removal vs the 955us version (numerics identical):
//  - Q fragments live in REGISTERS (loaded once via staging in the Ps region).
//  - K prefetched to registers one block ahead; STS at loop top.
//  - V copied with cp.async (raw f32) under the QK MMAs; tf32 cvt at PV load.
// Ps/Ks kperm layout (stride 72, conflict-free LDS.64); Vs raw f32 stride 72
// (PV B loads: banks 8c+g cover 0..31, conflict-free).
// Two __syncthreads per block:
//   S1 (after STS K / before QK): Ks ready, Vs safe to overwrite
//   S2 (after cp.async wait / before PV): Vs ready for everyone
// ============================================================================
#define ASTR  72
#define MQ    128

__global__ __launch_bounds__(256, 2)
void attn_tf32(const float* __restrict__ Qb, const float* __restrict__ Kb,
               const float* __restrict__ Vb, float* __restrict__ Ob) {
    extern __shared__ unsigned smA[];
    unsigned* Ps = smA;                 // [MQ][ASTR]  perm(key); also Q staging
    unsigned* Ks = Ps + MQ * ASTR;      // [64][ASTR]  perm(d)
    unsigned* Vs = Ks + 64 * ASTR;      // [64][ASTR]  raw f32, plain d
    float*    Vf = (float*)Vs;

    const int tid = threadIdx.x, lane = tid & 31, warp = tid >> 5;
    const int g = lane >> 2, c = lane & 3;
    const int h = blockIdx.y, q0 = blockIdx.x * MQ, c0 = h * DK;
    const int wq = warp * 16;

    const float QS = 0.125f * 1.4426950408889634f;   // (1/sqrt(dk)) * log2(e)

    // ---- stage Q (scaled, tf32, perm) into the Ps region : 8 passes ----
#pragma unroll
    for (int p = 0; p < (MQ * DK) / (256 * 4); p++) {
        const int idx = p * 1024 + tid * 4;
        const int r = idx >> 6, d0 = idx & 63;
        const float4 v = *(const float4*)(Qb + (q0 + r) * D_MODEL + c0 + d0);
        unsigned* dst = Ps + r * ASTR;
        const float vv[4] = {v.x, v.y, v.z, v.w};
#pragma unroll
        for (int j = 0; j < 4; j++) dst[kperm(d0 + j)] = f2tf(vv[j] * QS);
    }
    __syncthreads();

    // ---- hoist Q fragments into registers (once) ----
    unsigned qf[8][4];
#pragma unroll
    for (int s = 0; s < 8; s++) {
        const uint2 t0 = *(const uint2*)(Ps + (wq + g)     * ASTR + s * 8 + 2 * c);
        const uint2 t1 = *(const uint2*)(Ps + (wq + g + 8) * ASTR + s * 8 + 2 * c);
        qf[s][0] = t0.x; qf[s][1] = t1.x; qf[s][2] = t0.y; qf[s][3] = t1.y;
    }
    // (Ps rewritten only after S1+S2 barriers of block 0 -> no extra sync)

    // ---- prefetch K block 0 into registers ----
    float4 kreg[4];
#pragma unroll
    for (int p = 0; p < 4; p++) {
        const int idx = p * 1024 + tid * 4;
        const int r = idx >> 6, d0 = idx & 63;
        kreg[p] = *(const float4*)(Kb + r * D_MODEL + c0 + d0);
    }

    float o[8][4];
    float mrun[2], lrun[2];
    mrun[0] = mrun[1] = -1e30f;
    lrun[0] = lrun[1] = 0.0f;
#pragma unroll
    for (int na = 0; na < 8; na++)
#pragma unroll
        for (int r = 0; r < 4; r++) o[na][r] = 0.0f;

    const int pe = ((2 * c) & 3) * 2 + (((2 * c) >> 2) & 1);          // {0,4,1,5}
    const int po = ((2 * c + 1) & 3) * 2 + (((2 * c + 1) >> 2) & 1);  // {2,6,3,7}

    for (int kb = 0; kb < SEQ / 64; kb++) {
        const bool more = (kb + 1) < (SEQ / 64);

        // ---- STS K (block kb) from registers, kperm + tf32 ----
#pragma unroll
        for (int p = 0; p < 4; p++) {
            const int idx = p * 1024 + tid * 4;
            const int r = idx >> 6, d0 = idx & 63;
            unsigned* kd = Ks + r * ASTR;
            kd[kperm(d0 + 0)] = f2tf(kreg[p].x);
            kd[kperm(d0 + 1)] = f2tf(kreg[p].y);
            kd[kperm(d0 + 2)] = f2tf(kreg[p].z);
            kd[kperm(d0 + 3)] = f2tf(kreg[p].w);
        }

        // ---- prefetch K block kb+1 (latency hidden under whole block) ----
        if (more) {
            const int kr2 = (kb + 1) * 64;
#pragma unroll
            for (int p = 0; p < 4; p++) {
                const int idx = p * 1024 + tid * 4;
                const int r = idx >> 6, d0 = idx & 63;
                kreg[p] = *(const float4*)(Kb + (kr2 + r) * D_MODEL + c0 + d0);
            }
        }

        __syncthreads();   // S1: Ks visible; all PV readers of Vs are done

        // ---- V block kb via cp.async (runs under the QK MMAs) ----
        {
            const int kr = kb * 64;
#pragma unroll
            for (int p = 0; p < 4; p++) {
                const int idx = p * 1024 + tid * 4;
                const int r = idx >> 6, d0 = idx & 63;
                cp16(Vf + r * ASTR + d0, Vb + (kr + r) * D_MODEL + c0 + d0);
            }
            asm volatile("cp.async.commit_group;" ::: "memory");
        }

        // ---- S = Q K^T (per warp: 16 q-rows x 64 keys) ----
        float sa[8][4];
#pragma unroll
        for (int na = 0; na < 8; na++)
#pragma unroll
            for (int r = 0; r < 4; r++) sa[na][r] = 0.0f;

#pragma unroll
        for (int s = 0; s < 8; s++) {
#pragma unroll
            for (int na = 0; na < 8; na++) {
                const uint2 t = *(const uint2*)(Ks + (na * 8 + g) * ASTR + s * 8 + 2 * c);
                unsigned bk[2] = {t.x, t.y};
                mma8(sa[na], qf[s], bk);
            }
        }

        asm volatile("cp.async.wait_group 0;" ::: "memory");
        __syncthreads();   // S2: Vs ready for all warps

        // ---- online softmax (exp2 domain) + stage P (tf32, perm) ----
#pragma unroll
        for (int hf = 0; hf < 2; hf++) {
            float mx = -1e30f;
#pragma unroll
            for (int na = 0; na < 8; na++)
                mx = fmaxf(mx, fmaxf(sa[na][2 * hf], sa[na][2 * hf + 1]));
            mx = fmaxf(mx, __shfl_xor_sync(0xffffffffu, mx, 1));
            mx = fmaxf(mx, __shfl_xor_sync(0xffffffffu, mx, 2));
            const float mnew  = fmaxf(mrun[hf], mx);
            const float alpha = exp2f(mrun[hf] - mnew);
            mrun[hf] = mnew;

            float rs = 0.0f;
            unsigned* prow = Ps + (wq + hf * 8 + g) * ASTR;
#pragma unroll
            for (int na = 0; na < 8; na++) {
                const float p0 = exp2f(sa[na][2 * hf]     - mnew);
                const float p1 = exp2f(sa[na][2 * hf + 1] - mnew);
                rs += p0 + p1;
                prow[na * 8 + pe] = f2tf(p0);
                prow[na * 8 + po] = f2tf(p1);
                o[na][2 * hf]     *= alpha;
                o[na][2 * hf + 1] *= alpha;
            }
            rs += __shfl_xor_sync(0xffffffffu, rs, 1);
            rs += __shfl_xor_sync(0xffffffffu, rs, 2);
            lrun[hf] = lrun[hf] * alpha + rs;
        }
        __syncwarp();   // P rows are warp-local: cross-lane visibility only

        // ---- O += P V (contraction over 64 keys; cvt V at load) ----
#pragma unroll
        for (int s = 0; s < 8; s++) {
            unsigned ap[4];
            {
                const uint2 t0 = *(const uint2*)(Ps + (wq + g)     * ASTR + s * 8 + 2 * c);
                const uint2 t1 = *(const uint2*)(Ps + (wq + g + 8) * ASTR + s * 8 + 2 * c);
                ap[0] = t0.x; ap[1] = t1.x; ap[2] = t0.y; ap[3] = t1.y;
            }
#pragma unroll
            for (int na = 0; na < 8; na++) {
                unsigned bv[2];
                bv[0] = f2tf(Vf[(s * 8 + c)     * ASTR + na * 8 + g]);
                bv[1] = f2tf(Vf[(s * 8 + c + 4) * ASTR + na * 8 + g]);
                mma8(o[na], ap, bv);
            }
        }
        // next iteration's S1 protects Ks/Vs overwrite against slow PV readers
    }

    // ---- epilogue: O /= l, write concat-head layout [S, D_MODEL] ----
#pragma unroll
    for (int hf = 0; hf < 2; hf++) {
        const float inv = 1.0f / lrun[hf];
        const int row = q0 + wq + hf * 8 + g;
#pragma unroll
        for (int na = 0; na < 8; na++) {
            float2 w;
            w.x = o[na][2 * hf]     * inv;
            w.y = o[na][2 * hf + 1] * inv;
            *(float2*)(Ob + row * D_MODEL + c0 + na * 8 + 2 * c) = w;
        }
    }
}

// ============================================================================
// Launch
// ============================================================================
extern "C" void kernel_launch(void* const* d_in, const int* in_sizes, int n_in,
                              void* d_out, int out_size) {
    (void)in_sizes; (void)n_in; (void)out_size;
    const float* query = (const float*)d_in[0];
    const float* key   = (const float*)d_in[1];
    const float* value = (const float*)d_in[2];
    const float* Wq = (const float*)d_in[3];
    const float* bq = (const float*)d_in[4];
    const float* Wk = (const float*)d_in[5];
    const float* bk = (const float*)d_in[6];
    const float* Wv = (const float*)d_in[7];
    const float* bv = (const float*)d_in[8];
    const float* Wo = (const float*)d_in[9];
    const float* bo = (const float*)d_in[10];
    float* out = (float*)d_out;

    float *pQ, *pK, *pV, *pO;
    cudaGetSymbolAddress((void**)&pQ, g_Q);
    cudaGetSymbolAddress((void**)&pK, g_K);
    cudaGetSymbolAddress((void**)&pV, g_V);
    cudaGetSymbolAddress((void**)&pO, g_O);

    const int GSMEM = 4 * GBUF * (int)sizeof(unsigned);                  // 49152 B
    const int ASMEM = (MQ + 64 + 64) * ASTR * (int)sizeof(unsigned);     // 73728 B
    cudaFuncSetAttribute(gemm_qkv, cudaFuncAttributeMaxDynamicSharedMemorySize, GSMEM);
    cudaFuncSetAttribute(gemm_one, cudaFuncAttributeMaxDynamicSharedMemorySize, GSMEM);
    cudaFuncSetAttribute(attn_tf32, cudaFuncAttributeMaxDynamicSharedMemorySize, ASMEM);

    dim3 gq(D_MODEL / 128, SEQ / 128, 3);   // (8, 32, 3)
    gemm_qkv<<<gq, 256, GSMEM>>>(query, key, value, Wq, bq, Wk, bk, Wv, bv,
                                 pQ, pK, pV);

    dim3 ga(SEQ / MQ, NHEAD);               // (32, 16)
    attn_tf32<<<ga, 256, ASMEM>>>(pQ, pK, pV, pO);

    dim3 gg(D_MODEL / 128, SEQ / 128);      // (8, 32)
    gemm_one<<<gg, 256, GSMEM>>>(pO, Wo, bo, out);
}

// round 15
// speedup vs baseline: 1.0517x; 1.0517x over previous
#include <cuda_runtime.h>
#include <math.h>

#define D_MODEL 1024
#define SEQ     4096
#define NHEAD   16
#define DK      64

// Scratch (allocation-free: __device__ globals)
__device__ float g_Q[SEQ * D_MODEL];
__device__ float g_K[SEQ * D_MODEL];
__device__ float g_V[SEQ * D_MODEL];
__device__ float g_O[SEQ * D_MODEL];

// ---------------------------------------------------------------------------
// tf32 helpers. cvt.rna (round-to-nearest) is REQUIRED: raw-bit truncation in
// the mma gives a correlated -2^-11 bias per operand -> ~1e-3 systematic error.
// ---------------------------------------------------------------------------
__device__ __forceinline__ unsigned f2tf(float x) {
    unsigned y;
    asm("cvt.rna.tf32.f32 %0, %1;" : "=r"(y) : "f"(x));
    return y;
}

// D += A(16x8) * B(8x8), tf32 in, fp32 accum
__device__ __forceinline__ void mma8(float* d, const unsigned* a, const unsigned* b) {
    asm volatile(
        "mma.sync.aligned.m16n8k8.row.col.f32.tf32.tf32.f32 "
        "{%0,%1,%2,%3}, {%4,%5,%6,%7}, {%8,%9}, {%0,%1,%2,%3};\n"
        : "+f"(d[0]), "+f"(d[1]), "+f"(d[2]), "+f"(d[3])
        : "r"(a[0]), "r"(a[1]), "r"(a[2]), "r"(a[3]), "r"(b[0]), "r"(b[1]));
}

// Permutation within each 8-wide k-block so that the (c, c+4) fragment pair is
// adjacent in smem -> every fragment load is one LDS.64. (attention kernel)
__device__ __forceinline__ int kperm(int k) {
    return (k & ~7) + ((k & 3) << 1) + ((k >> 2) & 1);
}

// 16-byte async copy global -> shared (raw bits, no conversion)
__device__ __forceinline__ void cp16(const float* smem_dst, const float* gsrc) {
    unsigned saddr = (unsigned)__cvta_generic_to_shared(smem_dst);
    asm volatile("cp.async.ca.shared.global [%0], [%1], 16;"
                 :: "r"(saddr), "l"(gsrc));
}

// ============================================================================
// GEMM: C[M,1024] = A[M,1024] @ W[1024,1024]^T + bias  (tf32 mma, NT)
// Tile 128x128x16, 8 warps as 2(M)x4(N), warp tile 64x32.
// 4-STAGE cp.async pipeline: raw f32 lands in smem with ZERO staging registers;
// cvt.rna happens at fragment load (same rounding as before -> identical math).
// Plain layout, row stride 20 words: fragment banks (20g+c)%32 cover all 32
// lanes -> conflict-free scalar LDS; 20*16 % 32 == 0 keeps row offsets neutral.
// One wait_group<2> + __syncthreads per 16-k slab; 3 slabs always in flight.
// ============================================================================
#define GSTR2  20
#define GCH    (128 * GSTR2)     // words per matrix per stage (2560)
#define GSTAGE (2 * GCH)         // words per stage: A then B
#define NSTAGE 4
#define NSLAB  (D_MODEL / 16)    // 64
#define GSMEM  (NSTAGE * GSTAGE * (int)sizeof(float))   // 81920 B

__device__ __forceinline__ void gemm_core(const float* __restrict__ A,
                                          const float* __restrict__ W,
                                          const float* __restrict__ bias,
                                          float* __restrict__ C,
                                          int bx, int by) {
    extern __shared__ float gsm[];   // [NSTAGE][A:128x20 | B:128x20] raw f32

    const int tid  = threadIdx.x;
    const int lane = tid & 31;
    const int warp = tid >> 5;
    const int g = lane >> 2, c = lane & 3;
    const int wm = (warp >> 2) * 64;      // 0 / 64
    const int wn = (warp & 3) * 32;       // 0,32,64,96
    const int bm = by * 128;
    const int bn = bx * 128;

    // cp.async mapping: 2 chunks per thread per matrix per stage
    int rowp[2], jp[2];
#pragma unroll
    for (int p = 0; p < 2; p++) {
        const int lin = tid + p * 256;
        rowp[p] = lin >> 2;           // 0..127
        jp[p]   = (lin & 3) * 4;      // 0,4,8,12
    }

    float acc[4][4][4];
#pragma unroll
    for (int i = 0; i < 4; i++)
#pragma unroll
        for (int j = 0; j < 4; j++)
#pragma unroll
            for (int r = 0; r < 4; r++) acc[i][j][r] = 0.0f;

    // prologue: issue stages 0..2
#pragma unroll
    for (int s = 0; s < 3; s++) {
        float* st = gsm + s * GSTAGE;
#pragma unroll
        for (int p = 0; p < 2; p++) {
            cp16(st + rowp[p] * GSTR2 + jp[p],
                 A + (size_t)(bm + rowp[p]) * D_MODEL + s * 16 + jp[p]);
            cp16(st + GCH + rowp[p] * GSTR2 + jp[p],
                 W + (size_t)(bn + rowp[p]) * D_MODEL + s * 16 + jp[p]);
        }
        asm volatile("cp.async.commit_group;" ::: "memory");
    }

    for (int kc = 0; kc < NSLAB; kc++) {
        asm volatile("cp.async.wait_group 2;" ::: "memory");
        __syncthreads();   // stage kc visible to everyone; buffer (kc+3)%4 free

        // issue stage kc+3 (empty commit in tail keeps group accounting uniform)
        if (kc + 3 < NSLAB) {
            float* st = gsm + ((kc + 3) & 3) * GSTAGE;
            const int k0 = (kc + 3) * 16;
#pragma unroll
            for (int p = 0; p < 2; p++) {
                cp16(st + rowp[p] * GSTR2 + jp[p],
                     A + (size_t)(bm + rowp[p]) * D_MODEL + k0 + jp[p]);
                cp16(st + GCH + rowp[p] * GSTR2 + jp[p],
                     W + (size_t)(bn + rowp[p]) * D_MODEL + k0 + jp[p]);
            }
        }
        asm volatile("cp.async.commit_group;" ::: "memory");

        const float* Acur = gsm + (kc & 3) * GSTAGE;
        const float* Bcur = Acur + GCH;

#pragma unroll
        for (int s = 0; s < 2; s++) {
            unsigned af[4][4], bf[4][2];
#pragma unroll
            for (int ma = 0; ma < 4; ma++) {
                const int base = (wm + ma * 16 + g) * GSTR2 + s * 8 + c;
                af[ma][0] = f2tf(Acur[base]);
                af[ma][1] = f2tf(Acur[base + 8 * GSTR2]);
                af[ma][2] = f2tf(Acur[base + 4]);
                af[ma][3] = f2tf(Acur[base + 8 * GSTR2 + 4]);
            }
#pragma unroll
            for (int na = 0; na < 4; na++) {
                const int base = (wn + na * 8 + g) * GSTR2 + s * 8 + c;
                bf[na][0] = f2tf(Bcur[base]);
                bf[na][1] = f2tf(Bcur[base + 4]);
            }
#pragma unroll
            for (int ma = 0; ma < 4; ma++)
#pragma unroll
                for (int na = 0; na < 4; na++)
                    mma8(acc[ma][na], af[ma], bf[na]);
        }
        __syncthreads();   // all reads of stage kc done before it is rewritten
    }

    // epilogue: + bias, float2 stores
#pragma unroll
    for (int na = 0; na < 4; na++) {
        const int col = bn + wn + na * 8 + 2 * c;
        const float2 bb = *(const float2*)(bias + col);
#pragma unroll
        for (int ma = 0; ma < 4; ma++) {
            const int r0 = bm + wm + ma * 16 + g;
            float2 v0 = {acc[ma][na][0] + bb.x, acc[ma][na][1] + bb.y};
            float2 v1 = {acc[ma][na][2] + bb.x, acc[ma][na][3] + bb.y};
            *(float2*)(C + (size_t)r0 * D_MODEL + col)       = v0;
            *(float2*)(C + (size_t)(r0 + 8) * D_MODEL + col) = v1;
        }
    }
}

// Fused Q/K/V projection: blockIdx.z selects {query,key,value} x {Wq,Wk,Wv}.
__global__ __launch_bounds__(256, 2)
void gemm_qkv(const float* __restrict__ xq, const float* __restrict__ xk,
              const float* __restrict__ xv,
              const float* __restrict__ Wq, const float* __restrict__ bq,
              const float* __restrict__ Wk, const float* __restrict__ bk,
              const float* __restrict__ Wv, const float* __restrict__ bv,
              float* __restrict__ Cq, float* __restrict__ Ck, float* __restrict__ Cv) {
    const float *A, *W, *b;
    float* C;
    if (blockIdx.z == 0)      { A = xq; W = Wq; b = bq; C = Cq; }
    else if (blockIdx.z == 1) { A = xk; W = Wk; b = bk; C = Ck; }
    else                      { A = xv; W = Wv; b = bv; C = Cv; }
    gemm_core(A, W, b, C, blockIdx.x, blockIdx.y);
}

__global__ __launch_bounds__(256, 2)
void gemm_one(const float* __restrict__ A, const float* __restrict__ W,
              const float* __restrict__ bias, float* __restrict__ C) {
    gemm_core(A, W, bias, C, blockIdx.x, blockIdx.y);
}

// ============================================================================
// Flash attention, tf32 mma. (EXACT round-10 / 955us version — frozen.)
// One CTA = (head, 128-query block), 2 CTAs/SM. 8 warps x 16 query rows.
// ============================================================================
#define ASTR 72
#define MQ   128

__global__ __launch_bounds__(256, 2)
void attn_tf32(const float* __restrict__ Qb, const float* __restrict__ Kb,
               const float* __restrict__ Vb, float* __restrict__ Ob) {
    extern __shared__ unsigned smA[];
    unsigned* Qs = smA;                 // [MQ][ASTR]  perm(d)
    unsigned* Ps = Qs + MQ * ASTR;      // [MQ][ASTR]  perm(key)
    unsigned* Ks = Ps + MQ * ASTR;      // [64][ASTR]  perm(d)
    unsigned* Vs = Ks + 64 * ASTR;      // [64][ASTR]  plain d

    const int tid = threadIdx.x, lane = tid & 31, warp = tid >> 5;
    const int g = lane >> 2, c = lane & 3;
    const int h = blockIdx.y, q0 = blockIdx.x * MQ, c0 = h * DK;
    const int wq = warp * 16;

    const float QS = 0.125f * 1.4426950408889634f;   // (1/sqrt(dk)) * log2(e)

    // ---- stage Q (scaled, tf32, perm) : 8 passes ----
#pragma unroll
    for (int p = 0; p < (MQ * DK) / (256 * 4); p++) {
        const int idx = p * 1024 + tid * 4;
        const int r = idx >> 6, d0 = idx & 63;
        const float4 v = *(const float4*)(Qb + (q0 + r) * D_MODEL + c0 + d0);
        unsigned* dst = Qs + r * ASTR;
        const float vv[4] = {v.x, v.y, v.z, v.w};
#pragma unroll
        for (int j = 0; j < 4; j++) dst[kperm(d0 + j)] = f2tf(vv[j] * QS);
    }

    float o[8][4];
    float mrun[2], lrun[2];
    mrun[0] = mrun[1] = -1e30f;
    lrun[0] = lrun[1] = 0.0f;
#pragma unroll
    for (int na = 0; na < 8; na++)
#pragma unroll
        for (int r = 0; r < 4; r++) o[na][r] = 0.0f;

    const int pe = ((2 * c) & 3) * 2 + (((2 * c) >> 2) & 1);          // {0,4,1,5}
    const int po = ((2 * c + 1) & 3) * 2 + (((2 * c + 1) >> 2) & 1);  // {2,6,3,7}

    for (int kb = 0; kb < SEQ / 64; kb++) {
        const int kr = kb * 64;
        __syncthreads();   // previous PV readers of Ks/Vs done (covers Qs on kb=0)

        // ---- stage K (perm) and V (plain) : 4 passes ----
#pragma unroll
        for (int p = 0; p < 4; p++) {
            const int idx = p * 1024 + tid * 4;
            const int r = idx >> 6, d0 = idx & 63;
            const float4 kv = *(const float4*)(Kb + (kr + r) * D_MODEL + c0 + d0);
            unsigned* kd = Ks + r * ASTR;
            kd[kperm(d0 + 0)] = f2tf(kv.x);
            kd[kperm(d0 + 1)] = f2tf(kv.y);
            kd[kperm(d0 + 2)] = f2tf(kv.z);
            kd[kperm(d0 + 3)] = f2tf(kv.w);
            const float4 vv = *(const float4*)(Vb + (kr + r) * D_MODEL + c0 + d0);
            uint4 vt;
            vt.x = f2tf(vv.x); vt.y = f2tf(vv.y); vt.z = f2tf(vv.z); vt.w = f2tf(vv.w);
            *(uint4*)(Vs + r * ASTR + d0) = vt;
        }
        __syncthreads();

        // ---- S = Q K^T (per warp: 16 q-rows x 64 keys) ----
        float sa[8][4];
#pragma unroll
        for (int na = 0; na < 8; na++)
#pragma unroll
            for (int r = 0; r < 4; r++) sa[na][r] = 0.0f;

#pragma unroll
        for (int s = 0; s < 8; s++) {
            unsigned aq[4];
            {
                const uint2 t0 = *(const uint2*)(Qs + (wq + g)     * ASTR + s * 8 + 2 * c);
                const uint2 t1 = *(const uint2*)(Qs + (wq + g + 8) * ASTR + s * 8 + 2 * c);
                aq[0] = t0.x; aq[1] = t1.x; aq[2] = t0.y; aq[3] = t1.y;
            }
#pragma unroll
            for (int na = 0; na < 8; na++) {
                const uint2 t = *(const uint2*)(Ks + (na * 8 + g) * ASTR + s * 8 + 2 * c);
                unsigned bk[2] = {t.x, t.y};
                mma8(sa[na], aq, bk);
            }
        }

        // ---- online softmax (exp2 domain) + stage P (tf32, perm) ----
#pragma unroll
        for (int hf = 0; hf < 2; hf++) {
            float mx = -1e30f;
#pragma unroll
            for (int na = 0; na < 8; na++)
                mx = fmaxf(mx, fmaxf(sa[na][2 * hf], sa[na][2 * hf + 1]));
            mx = fmaxf(mx, __shfl_xor_sync(0xffffffffu, mx, 1));
            mx = fmaxf(mx, __shfl_xor_sync(0xffffffffu, mx, 2));
            const float mnew  = fmaxf(mrun[hf], mx);
            const float alpha = exp2f(mrun[hf] - mnew);
            mrun[hf] = mnew;

            float rs = 0.0f;
            unsigned* prow = Ps + (wq + hf * 8 + g) * ASTR;
#pragma unroll
            for (int na = 0; na < 8; na++) {
                const float p0 = exp2f(sa[na][2 * hf]     - mnew);
                const float p1 = exp2f(sa[na][2 * hf + 1] - mnew);
                rs += p0 + p1;
                prow[na * 8 + pe] = f2tf(p0);
                prow[na * 8 + po] = f2tf(p1);
                o[na][2 * hf]     *= alpha;
                o[na][2 * hf + 1] *= alpha;
            }
            rs += __shfl_xor_sync(0xffffffffu, rs, 1);
            rs += __shfl_xor_sync(0xffffffffu, rs, 2);
            lrun[hf] = lrun[hf] * alpha + rs;
        }
        __syncwarp();   // P rows are warp-local: cross-lane visibility only

        // ---- O += P V (contraction over 64 keys) ----
#pragma unroll
        for (int s = 0; s < 8; s++) {
            unsigned ap[4];
            {
                const uint2 t0 = *(const uint2*)(Ps + (wq + g)     * ASTR + s * 8 + 2 * c);
                const uint2 t1 = *(const uint2*)(Ps + (wq + g + 8) * ASTR + s * 8 + 2 * c);
                ap[0] = t0.x; ap[1] = t1.x; ap[2] = t0.y; ap[3] = t1.y;
            }
#pragma unroll
            for (int na = 0; na < 8; na++) {
                unsigned bv[2];
                bv[0] = Vs[(s * 8 + c)     * ASTR + na * 8 + g];
                bv[1] = Vs[(s * 8 + c + 4) * ASTR + na * 8 + g];
                mma8(o[na], ap, bv);
            }
        }
    }

    // ---- epilogue: O /= l, write concat-head layout [S, D_MODEL] ----
#pragma unroll
    for (int hf = 0; hf < 2; hf++) {
        const float inv = 1.0f / lrun[hf];
        const int row = q0 + wq + hf * 8 + g;
#pragma unroll
        for (int na = 0; na < 8; na++) {
            float2 w;
            w.x = o[na][2 * hf]     * inv;
            w.y = o[na][2 * hf + 1] * inv;
            *(float2*)(Ob + row * D_MODEL + c0 + na * 8 + 2 * c) = w;
        }
    }
}

// ============================================================================
// Launch
// ============================================================================
extern "C" void kernel_launch(void* const* d_in, const int* in_sizes, int n_in,
                              void* d_out, int out_size) {
    (void)in_sizes; (void)n_in; (void)out_size;
    const float* query = (const float*)d_in[0];
    const float* key   = (const float*)d_in[1];
    const float* value = (const float*)d_in[2];
    const float* Wq = (const float*)d_in[3];
    const float* bq = (const float*)d_in[4];
    const float* Wk = (const float*)d_in[5];
    const float* bk = (const float*)d_in[6];
    const float* Wv = (const float*)d_in[7];
    const float* bv = (const float*)d_in[8];
    const float* Wo = (const float*)d_in[9];
    const float* bo = (const float*)d_in[10];
    float* out = (float*)d_out;

    float *pQ, *pK, *pV, *pO;
    cudaGetSymbolAddress((void**)&pQ, g_Q);
    cudaGetSymbolAddress((void**)&pK, g_K);
    cudaGetSymbolAddress((void**)&pV, g_V);
    cudaGetSymbolAddress((void**)&pO, g_O);

    const int ASMEM = (2 * MQ + 2 * 64) * ASTR * (int)sizeof(unsigned);  // 110592 B
    cudaFuncSetAttribute(gemm_qkv, cudaFuncAttributeMaxDynamicSharedMemorySize, GSMEM);
    cudaFuncSetAttribute(gemm_one, cudaFuncAttributeMaxDynamicSharedMemorySize, GSMEM);
    cudaFuncSetAttribute(attn_tf32, cudaFuncAttributeMaxDynamicSharedMemorySize, ASMEM);

    dim3 gq(D_MODEL / 128, SEQ / 128, 3);   // (8, 32, 3)
    gemm_qkv<<<gq, 256, GSMEM>>>(query, key, value, Wq, bq, Wk, bk, Wv, bv,
                                 pQ, pK, pV);

    dim3 ga(SEQ / MQ, NHEAD);               // (32, 16)
    attn_tf32<<<ga, 256, ASMEM>>>(pQ, pK, pV, pO);

    dim3 gg(D_MODEL / 128, SEQ / 128);      // (8, 32)
    gemm_one<<<gg, 256, GSMEM>>>(pO, Wo, bo, out);
}

// round 16
// speedup vs baseline: 1.1239x; 1.0686x over previous
#include <cuda_runtime.h>
#include <math.h>

#define D_MODEL 1024
#define SEQ     4096
#define NHEAD   16
#define DK      64

// Scratch (allocation-free: __device__ globals)
__device__ float g_Q[SEQ * D_MODEL];
__device__ float g_K[SEQ * D_MODEL];
__device__ float g_V[SEQ * D_MODEL];
__device__ float g_O[SEQ * D_MODEL];

// ---------------------------------------------------------------------------
// tf32 helpers. cvt.rna (round-to-nearest) is REQUIRED: raw-bit truncation in
// the mma gives a correlated -2^-11 bias per operand -> ~1e-3 systematic error.
// ---------------------------------------------------------------------------
__device__ __forceinline__ unsigned f2tf(float x) {
    unsigned y;
    asm("cvt.rna.tf32.f32 %0, %1;" : "=r"(y) : "f"(x));
    return y;
}

// D += A(16x8) * B(8x8), tf32 in, fp32 accum
__device__ __forceinline__ void mma8(float* d, const unsigned* a, const unsigned* b) {
    asm volatile(
        "mma.sync.aligned.m16n8k8.row.col.f32.tf32.tf32.f32 "
        "{%0,%1,%2,%3}, {%4,%5,%6,%7}, {%8,%9}, {%0,%1,%2,%3};\n"
        : "+f"(d[0]), "+f"(d[1]), "+f"(d[2]), "+f"(d[3])
        : "r"(a[0]), "r"(a[1]), "r"(a[2]), "r"(a[3]), "r"(b[0]), "r"(b[1]));
}

// Permutation within each 8-wide k-block so that the (c, c+4) fragment pair is
// adjacent in smem -> every fragment load is one LDS.64. (attention kernel)
__device__ __forceinline__ int kperm(int k) {
    return (k & ~7) + ((k & 3) << 1) + ((k >> 2) & 1);
}

// 16-byte async copy global -> shared (raw bits, no conversion)
__device__ __forceinline__ void cp16(const float* smem_dst, const float* gsrc) {
    unsigned saddr = (unsigned)__cvta_generic_to_shared(smem_dst);
    asm volatile("cp.async.ca.shared.global [%0], [%1], 16;"
                 :: "r"(saddr), "l"(gsrc));
}

// ============================================================================
// GEMM: C[M,1024] = A[M,1024] @ W[1024,1024]^T + bias  (tf32 mma, NT)
// Tile 128x128xBK32, 8 warps as 2(M)x4(N), warp tile 64x32.
// 2-stage cp.async pipeline, ONE barrier + ONE wait per 32-wide slab:
//   wait_group 0        -> own copies of slab kc landed
//   __syncthreads       -> slab kc visible to all; compute(kc-1) done by all
//   issue copy(kc+1)    -> flies during compute(kc) (64 MMAs >> L2 latency)
//   compute(kc)
// Row stride 36 words: fragment banks (36g+c)%32 = 4g+c cover 0..31 exactly
// -> every scalar LDS is conflict-free; 36*16 % 32 == 0 keeps rows neutral.
// cvt.rna at fragment load (numerics identical to previous rounds).
// ============================================================================
#define GSTR3 36
#define GCH3  (128 * GSTR3)      // words per matrix per stage (4608)
#define GSTG3 (2 * GCH3)         // words per stage: A then B (9216)
#define NSLAB (D_MODEL / 32)     // 32
#define GSMEM (2 * GSTG3 * (int)sizeof(float))   // 73728 B -> 2 CTAs/SM

__device__ __forceinline__ void gemm_core(const float* __restrict__ A,
                                          const float* __restrict__ W,
                                          const float* __restrict__ bias,
                                          float* __restrict__ C,
                                          int bx, int by) {
    extern __shared__ float gsm[];   // [2][A:128x36 | B:128x36] raw f32

    const int tid  = threadIdx.x;
    const int lane = tid & 31;
    const int warp = tid >> 5;
    const int g = lane >> 2, c = lane & 3;
    const int wm = (warp >> 2) * 64;      // 0 / 64
    const int wn = (warp & 3) * 32;       // 0,32,64,96
    const int bm = by * 128;
    const int bn = bx * 128;

    // cp.async mapping: 4 chunks per thread per matrix per stage (128x32 f32)
    int rowp[4], jp[4];
#pragma unroll
    for (int p = 0; p < 4; p++) {
        const int lin = tid + p * 256;
        rowp[p] = lin >> 3;           // 0..127
        jp[p]   = (lin & 7) * 4;      // 0,4,...,28
    }

    float acc[4][4][4];
#pragma unroll
    for (int i = 0; i < 4; i++)
#pragma unroll
        for (int j = 0; j < 4; j++)
#pragma unroll
            for (int r = 0; r < 4; r++) acc[i][j][r] = 0.0f;

    // prologue: issue slab 0 into stage 0
    {
        float* st = gsm;
#pragma unroll
        for (int p = 0; p < 4; p++) {
            cp16(st + rowp[p] * GSTR3 + jp[p],
                 A + (size_t)(bm + rowp[p]) * D_MODEL + jp[p]);
            cp16(st + GCH3 + rowp[p] * GSTR3 + jp[p],
                 W + (size_t)(bn + rowp[p]) * D_MODEL + jp[p]);
        }
        asm volatile("cp.async.commit_group;" ::: "memory");
    }

    for (int kc = 0; kc < NSLAB; kc++) {
        asm volatile("cp.async.wait_group 0;" ::: "memory");
        __syncthreads();   // slab kc visible to all; compute(kc-1) done by all

        // issue slab kc+1 into the other stage (flies during compute below)
        if (kc + 1 < NSLAB) {
            float* st = gsm + ((kc + 1) & 1) * GSTG3;
            const int k0 = (kc + 1) * 32;
#pragma unroll
            for (int p = 0; p < 4; p++) {
                cp16(st + rowp[p] * GSTR3 + jp[p],
                     A + (size_t)(bm + rowp[p]) * D_MODEL + k0 + jp[p]);
                cp16(st + GCH3 + rowp[p] * GSTR3 + jp[p],
                     W + (size_t)(bn + rowp[p]) * D_MODEL + k0 + jp[p]);
            }
            asm volatile("cp.async.commit_group;" ::: "memory");
        }

        const float* Acur = gsm + (kc & 1) * GSTG3;
        const float* Bcur = Acur + GCH3;

#pragma unroll
        for (int s = 0; s < 4; s++) {
            unsigned af[4][4], bf[4][2];
#pragma unroll
            for (int ma = 0; ma < 4; ma++) {
                const int base = (wm + ma * 16 + g) * GSTR3 + s * 8 + c;
                af[ma][0] = f2tf(Acur[base]);
                af[ma][1] = f2tf(Acur[base + 8 * GSTR3]);
                af[ma][2] = f2tf(Acur[base + 4]);
                af[ma][3] = f2tf(Acur[base + 8 * GSTR3 + 4]);
            }
#pragma unroll
            for (int na = 0; na < 4; na++) {
                const int base = (wn + na * 8 + g) * GSTR3 + s * 8 + c;
                bf[na][0] = f2tf(Bcur[base]);
                bf[na][1] = f2tf(Bcur[base + 4]);
            }
#pragma unroll
            for (int ma = 0; ma < 4; ma++)
#pragma unroll
                for (int na = 0; na < 4; na++)
                    mma8(acc[ma][na], af[ma], bf[na]);
        }
        // no trailing barrier: next iteration's wait+sync provides all ordering
    }

    // epilogue: + bias, float2 stores
#pragma unroll
    for (int na = 0; na < 4; na++) {
        const int col = bn + wn + na * 8 + 2 * c;
        const float2 bb = *(const float2*)(bias + col);
#pragma unroll
        for (int ma = 0; ma < 4; ma++) {
            const int r0 = bm + wm + ma * 16 + g;
            float2 v0 = {acc[ma][na][0] + bb.x, acc[ma][na][1] + bb.y};
            float2 v1 = {acc[ma][na][2] + bb.x, acc[ma][na][3] + bb.y};
            *(float2*)(C + (size_t)r0 * D_MODEL + col)       = v0;
            *(float2*)(C + (size_t)(r0 + 8) * D_MODEL + col) = v1;
        }
    }
}

// Fused Q/K/V projection: blockIdx.z selects {query,key,value} x {Wq,Wk,Wv}.
__global__ __launch_bounds__(256, 2)
void gemm_qkv(const float* __restrict__ xq, const float* __restrict__ xk,
              const float* __restrict__ xv,
              const float* __restrict__ Wq, const float* __restrict__ bq,
              const float* __restrict__ Wk, const float* __restrict__ bk,
              const float* __restrict__ Wv, const float* __restrict__ bv,
              float* __restrict__ Cq, float* __restrict__ Ck, float* __restrict__ Cv) {
    const float *A, *W, *b;
    float* C;
    if (blockIdx.z == 0)      { A = xq; W = Wq; b = bq; C = Cq; }
    else if (blockIdx.z == 1) { A = xk; W = Wk; b = bk; C = Ck; }
    else                      { A = xv; W = Wv; b = bv; C = Cv; }
    gemm_core(A, W, b, C, blockIdx.x, blockIdx.y);
}

__global__ __launch_bounds__(256, 2)
void gemm_one(const float* __restrict__ A, const float* __restrict__ W,
              const float* __restrict__ bias, float* __restrict__ C) {
    gemm_core(A, W, bias, C, blockIdx.x, blockIdx.y);
}

// ============================================================================
// Flash attention, tf32 mma. (EXACT round-10 / 955us version — frozen.)
// One CTA = (head, 128-query block), 2 CTAs/SM. 8 warps x 16 query rows.
// ============================================================================
#define ASTR 72
#define MQ   128

__global__ __launch_bounds__(256, 2)
void attn_tf32(const float* __restrict__ Qb, const float* __restrict__ Kb,
               const float* __restrict__ Vb, float* __restrict__ Ob) {
    extern __shared__ unsigned smA[];
    unsigned* Qs = smA;                 // [MQ][ASTR]  perm(d)
    unsigned* Ps = Qs + MQ * ASTR;      // [MQ][ASTR]  perm(key)
    unsigned* Ks = Ps + MQ * ASTR;      // [64][ASTR]  perm(d)
    unsigned* Vs = Ks + 64 * ASTR;      // [64][ASTR]  plain d

    const int tid = threadIdx.x, lane = tid & 31, warp = tid >> 5;
    const int g = lane >> 2, c = lane & 3;
    const int h = blockIdx.y, q0 = blockIdx.x * MQ, c0 = h * DK;
    const int wq = warp * 16;

    const float QS = 0.125f * 1.4426950408889634f;   // (1/sqrt(dk)) * log2(e)

    // ---- stage Q (scaled, tf32, perm) : 8 passes ----
#pragma unroll
    for (int p = 0; p < (MQ * DK) / (256 * 4); p++) {
        const int idx = p * 1024 + tid * 4;
        const int r = idx >> 6, d0 = idx & 63;
        const float4 v = *(const float4*)(Qb + (q0 + r) * D_MODEL + c0 + d0);
        unsigned* dst = Qs + r * ASTR;
        const float vv[4] = {v.x, v.y, v.z, v.w};
#pragma unroll
        for (int j = 0; j < 4; j++) dst[kperm(d0 + j)] = f2tf(vv[j] * QS);
    }

    float o[8][4];
    float mrun[2], lrun[2];
    mrun[0] = mrun[1] = -1e30f;
    lrun[0] = lrun[1] = 0.0f;
#pragma unroll
    for (int na = 0; na < 8; na++)
#pragma unroll
        for (int r = 0; r < 4; r++) o[na][r] = 0.0f;

    const int pe = ((2 * c) & 3) * 2 + (((2 * c) >> 2) & 1);          // {0,4,1,5}
    const int po = ((2 * c + 1) & 3) * 2 + (((2 * c + 1) >> 2) & 1);  // {2,6,3,7}

    for (int kb = 0; kb < SEQ / 64; kb++) {
        const int kr = kb * 64;
        __syncthreads();   // previous PV readers of Ks/Vs done (covers Qs on kb=0)

        // ---- stage K (perm) and V (plain) : 4 passes ----
#pragma unroll
        for (int p = 0; p < 4; p++) {
            const int idx = p * 1024 + tid * 4;
            const int r = idx >> 6, d0 = idx & 63;
            const float4 kv = *(const float4*)(Kb + (kr + r) * D_MODEL + c0 + d0);
            unsigned* kd = Ks + r * ASTR;
            kd[kperm(d0 + 0)] = f2tf(kv.x);
            kd[kperm(d0 + 1)] = f2tf(kv.y);
            kd[kperm(d0 + 2)] = f2tf(kv.z);
            kd[kperm(d0 + 3)] = f2tf(kv.w);
            const float4 vv = *(const float4*)(Vb + (kr + r) * D_MODEL + c0 + d0);
            uint4 vt;
            vt.x = f2tf(vv.x); vt.y = f2tf(vv.y); vt.z = f2tf(vv.z); vt.w = f2tf(vv.w);
            *(uint4*)(Vs + r * ASTR + d0) = vt;
        }
        __syncthreads();

        // ---- S = Q K^T (per warp: 16 q-rows x 64 keys) ----
        float sa[8][4];
#pragma unroll
        for (int na = 0; na < 8; na++)
#pragma unroll
            for (int r = 0; r < 4; r++) sa[na][r] = 0.0f;

#pragma unroll
        for (int s = 0; s < 8; s++) {
            unsigned aq[4];
            {
                const uint2 t0 = *(const uint2*)(Qs + (wq + g)     * ASTR + s * 8 + 2 * c);
                const uint2 t1 = *(const uint2*)(Qs + (wq + g + 8) * ASTR + s * 8 + 2 * c);
                aq[0] = t0.x; aq[1] = t1.x; aq[2] = t0.y; aq[3] = t1.y;
            }
#pragma unroll
            for (int na = 0; na < 8; na++) {
                const uint2 t = *(const uint2*)(Ks + (na * 8 + g) * ASTR + s * 8 + 2 * c);
                unsigned bk[2] = {t.x, t.y};
                mma8(sa[na], aq, bk);
            }
        }

        // ---- online softmax (exp2 domain) + stage P (tf32, perm) ----
#pragma unroll
        for (int hf = 0; hf < 2; hf++) {
            float mx = -1e30f;
#pragma unroll
            for (int na = 0; na < 8; na++)
                mx = fmaxf(mx, fmaxf(sa[na][2 * hf], sa[na][2 * hf + 1]));
            mx = fmaxf(mx, __shfl_xor_sync(0xffffffffu, mx, 1));
            mx = fmaxf(mx, __shfl_xor_sync(0xffffffffu, mx, 2));
            const float mnew  = fmaxf(mrun[hf], mx);
            const float alpha = exp2f(mrun[hf] - mnew);
            mrun[hf] = mnew;

            float rs = 0.0f;
            unsigned* prow = Ps + (wq + hf * 8 + g) * ASTR;
#pragma unroll
            for (int na = 0; na < 8; na++) {
                const float p0 = exp2f(sa[na][2 * hf]     - mnew);
                const float p1 = exp2f(sa[na][2 * hf + 1] - mnew);
                rs += p0 + p1;
                prow[na * 8 + pe] = f2tf(p0);
                prow[na * 8 + po] = f2tf(p1);
                o[na][2 * hf]     *= alpha;
                o[na][2 * hf + 1] *= alpha;
            }
            rs += __shfl_xor_sync(0xffffffffu, rs, 1);
            rs += __shfl_xor_sync(0xffffffffu, rs, 2);
            lrun[hf] = lrun[hf] * alpha + rs;
        }
        __syncwarp();   // P rows are warp-local: cross-lane visibility only

        // ---- O += P V (contraction over 64 keys) ----
#pragma unroll
        for (int s = 0; s < 8; s++) {
            unsigned ap[4];
            {
                const uint2 t0 = *(const uint2*)(Ps + (wq + g)     * ASTR + s * 8 + 2 * c);
                const uint2 t1 = *(const uint2*)(Ps + (wq + g + 8) * ASTR + s * 8 + 2 * c);
                ap[0] = t0.x; ap[1] = t1.x; ap[2] = t0.y; ap[3] = t1.y;
            }
#pragma unroll
            for (int na = 0; na < 8; na++) {
                unsigned bv[2];
                bv[0] = Vs[(s * 8 + c)     * ASTR + na * 8 + g];
                bv[1] = Vs[(s * 8 + c + 4) * ASTR + na * 8 + g];
                mma8(o[na], ap, bv);
            }
        }
    }

    // ---- epilogue: O /= l, write concat-head layout [S, D_MODEL] ----
#pragma unroll
    for (int hf = 0; hf < 2; hf++) {
        const float inv = 1.0f / lrun[hf];
        const int row = q0 + wq + hf * 8 + g;
#pragma unroll
        for (int na = 0; na < 8; na++) {
            float2 w;
            w.x = o[na][2 * hf]     * inv;
            w.y = o[na][2 * hf + 1] * inv;
            *(float2*)(Ob + row * D_MODEL + c0 + na * 8 + 2 * c) = w;
        }
    }
}

// ============================================================================
// Launch
// ============================================================================
extern "C" void kernel_launch(void* const* d_in, const int* in_sizes, int n_in,
                              void* d_out, int out_size) {
    (void)in_sizes; (void)n_in; (void)out_size;
    const float* query = (const float*)d_in[0];
    const float* key   = (const float*)d_in[1];
    const float* value = (const float*)d_in[2];
    const float* Wq = (const float*)d_in[3];
    const float* bq = (const float*)d_in[4];
    const float* Wk = (const float*)d_in[5];
    const float* bk = (const float*)d_in[6];
    const float* Wv = (const float*)d_in[7];
    const float* bv = (const float*)d_in[8];
    const float* Wo = (const float*)d_in[9];
    const float* bo = (const float*)d_in[10];
    float* out = (float*)d_out;

    float *pQ, *pK, *pV, *pO;
    cudaGetSymbolAddress((void**)&pQ, g_Q);
    cudaGetSymbolAddress((void**)&pK, g_K);
    cudaGetSymbolAddress((void**)&pV, g_V);
    cudaGetSymbolAddress((void**)&pO, g_O);

    const int ASMEM = (2 * MQ + 2 * 64) * ASTR * (int)sizeof(unsigned);  // 110592 B
    cudaFuncSetAttribute(gemm_qkv, cudaFuncAttributeMaxDynamicSharedMemorySize, GSMEM);
    cudaFuncSetAttribute(gemm_one, cudaFuncAttributeMaxDynamicSharedMemorySize, GSMEM);
    cudaFuncSetAttribute(attn_tf32, cudaFuncAttributeMaxDynamicSharedMemorySize, ASMEM);

    dim3 gq(D_MODEL / 128, SEQ / 128, 3);   // (8, 32, 3)
    gemm_qkv<<<gq, 256, GSMEM>>>(query, key, value, Wq, bq, Wk, bk, Wv, bv,
                                 pQ, pK, pV);

    dim3 ga(SEQ / MQ, NHEAD);               // (32, 16)
    attn_tf32<<<ga, 256, ASMEM>>>(pQ, pK, pV, pO);

    dim3 gg(D_MODEL / 128, SEQ / 128);      // (8, 32)
    gemm_one<<<gg, 256, GSMEM>>>(pO, Wo, bo, out);
}